// round 2
// baseline (speedup 1.0000x reference)
#include <cuda_runtime.h>
#include <math.h>

// Problem constants
#define BB 4
#define HH 16
#define SS 2048
#define DD 1024
#define HD 64
#define MROWS (BB * SS)   // 8192

// ---------------------------------------------------------------------------
// Scratch (no allocations allowed -> __device__ globals)
// ---------------------------------------------------------------------------
__device__ float g_Q[BB * HH * SS * HD];
__device__ float g_K[BB * HH * SS * HD];
__device__ float g_V[BB * HH * SS * HD];
__device__ float g_ctx[BB * SS * DD];

// ---------------------------------------------------------------------------
// GEMM: Y[m][n] = sum_k X[m][k] * W[n][k] + bias[n]
// M=8192, N=1024, K=1024. BM=BN=64, BK=16, 256 threads, 4x4 per thread.
// Double-buffered smem with register prefetch.
// If BHSD: write to [B, H, S, hd] layout (each 64-wide N tile == one head).
// ---------------------------------------------------------------------------
template <bool BHSD>
__global__ __launch_bounds__(256) void gemm_bias_kernel(
    const float* __restrict__ X, const float* __restrict__ W,
    const float* __restrict__ bias, float* __restrict__ Y)
{
    const int Kdim = 1024;
    __shared__ __align__(16) float As[2][16][68];
    __shared__ __align__(16) float Bs[2][16][68];

    const int tid = threadIdx.x;
    const int tx = tid & 15;        // 0..15 -> n subtile
    const int ty = tid >> 4;        // 0..15 -> m subtile
    const int m0 = blockIdx.y * 64;
    const int n0 = blockIdx.x * 64;

    const int lrow = tid >> 2;      // 0..63
    const int lk4  = (tid & 3) * 4; // 0,4,8,12

    const float* Xp = X + (size_t)(m0 + lrow) * Kdim + lk4;
    const float* Wp = W + (size_t)(n0 + lrow) * Kdim + lk4;

    // prologue: load tile 0
    float4 a = *(const float4*)Xp;
    float4 b = *(const float4*)Wp;
    As[0][lk4 + 0][lrow] = a.x; As[0][lk4 + 1][lrow] = a.y;
    As[0][lk4 + 2][lrow] = a.z; As[0][lk4 + 3][lrow] = a.w;
    Bs[0][lk4 + 0][lrow] = b.x; Bs[0][lk4 + 1][lrow] = b.y;
    Bs[0][lk4 + 2][lrow] = b.z; Bs[0][lk4 + 3][lrow] = b.w;
    __syncthreads();

    float acc[4][4];
#pragma unroll
    for (int i = 0; i < 4; ++i)
#pragma unroll
        for (int j = 0; j < 4; ++j) acc[i][j] = 0.0f;

    int buf = 0;
    for (int kt = 0; kt < 64; ++kt) {
        if (kt < 63) {
            a = *(const float4*)(Xp + (kt + 1) * 16);
            b = *(const float4*)(Wp + (kt + 1) * 16);
        }
#pragma unroll
        for (int kk = 0; kk < 16; ++kk) {
            float4 av = *(const float4*)&As[buf][kk][ty * 4];
            float4 bv = *(const float4*)&Bs[buf][kk][tx * 4];
            acc[0][0] = fmaf(av.x, bv.x, acc[0][0]);
            acc[0][1] = fmaf(av.x, bv.y, acc[0][1]);
            acc[0][2] = fmaf(av.x, bv.z, acc[0][2]);
            acc[0][3] = fmaf(av.x, bv.w, acc[0][3]);
            acc[1][0] = fmaf(av.y, bv.x, acc[1][0]);
            acc[1][1] = fmaf(av.y, bv.y, acc[1][1]);
            acc[1][2] = fmaf(av.y, bv.z, acc[1][2]);
            acc[1][3] = fmaf(av.y, bv.w, acc[1][3]);
            acc[2][0] = fmaf(av.z, bv.x, acc[2][0]);
            acc[2][1] = fmaf(av.z, bv.y, acc[2][1]);
            acc[2][2] = fmaf(av.z, bv.z, acc[2][2]);
            acc[2][3] = fmaf(av.z, bv.w, acc[2][3]);
            acc[3][0] = fmaf(av.w, bv.x, acc[3][0]);
            acc[3][1] = fmaf(av.w, bv.y, acc[3][1]);
            acc[3][2] = fmaf(av.w, bv.z, acc[3][2]);
            acc[3][3] = fmaf(av.w, bv.w, acc[3][3]);
        }
        if (kt < 63) {
            int nb = buf ^ 1;
            As[nb][lk4 + 0][lrow] = a.x; As[nb][lk4 + 1][lrow] = a.y;
            As[nb][lk4 + 2][lrow] = a.z; As[nb][lk4 + 3][lrow] = a.w;
            Bs[nb][lk4 + 0][lrow] = b.x; Bs[nb][lk4 + 1][lrow] = b.y;
            Bs[nb][lk4 + 2][lrow] = b.z; Bs[nb][lk4 + 3][lrow] = b.w;
        }
        buf ^= 1;
        __syncthreads();
    }

    // epilogue
    float bv0 = bias[n0 + tx * 4 + 0];
    float bv1 = bias[n0 + tx * 4 + 1];
    float bv2 = bias[n0 + tx * 4 + 2];
    float bv3 = bias[n0 + tx * 4 + 3];

#pragma unroll
    for (int i = 0; i < 4; ++i) {
        int m = m0 + ty * 4 + i;
        float4 o;
        o.x = acc[i][0] + bv0;
        o.y = acc[i][1] + bv1;
        o.z = acc[i][2] + bv2;
        o.w = acc[i][3] + bv3;
        if (BHSD) {
            int bidx = m >> 11;          // / 2048
            int s = m & 2047;
            int h = blockIdx.x;          // n0/64
            float* dst = Y + (((size_t)(bidx * HH + h) * SS) + s) * HD + tx * 4;
            *(float4*)dst = o;
        } else {
            *(float4*)(Y + (size_t)m * DD + n0 + tx * 4) = o;
        }
    }
}

// ---------------------------------------------------------------------------
// RoPE in-place on [B, H, S, 64]. One thread handles an (i, i+32) pair.
// cos/sin are [S, 64] with identical halves.
// ---------------------------------------------------------------------------
__global__ void rope_kernel(float* __restrict__ P,
                            const float* __restrict__ cosb,
                            const float* __restrict__ sinb)
{
    int idx = blockIdx.x * blockDim.x + threadIdx.x; // < B*H*S*32
    int i = idx & 31;
    int bhs = idx >> 5;
    int s = bhs & (SS - 1);
    float* p = P + (size_t)bhs * HD;
    float x0 = p[i];
    float x1 = p[i + 32];
    float c  = cosb[s * HD + i];
    float sn = sinb[s * HD + i];
    p[i]      = x0 * c - x1 * sn;
    p[i + 32] = x1 * c + x0 * sn;
}

// ---------------------------------------------------------------------------
// Causal flash attention, fp32. Block: 256 threads (16x16), BM=BN=64, HD=64.
// Q/K in smem transposed (stride 68 -> aligned float4, conflict-free).
// P transposed (stride 68), V row-major.
// ---------------------------------------------------------------------------
#define FLASH_SMEM_FLOATS (3 * 64 * 68 + 64 * 64)
#define FLASH_SMEM_BYTES  (FLASH_SMEM_FLOATS * 4)

__global__ __launch_bounds__(256) void flash_kernel(
    const float* __restrict__ Q, const float* __restrict__ K,
    const float* __restrict__ V, float* __restrict__ O)
{
    extern __shared__ __align__(16) float sm[];
    float* Qt = sm;                 // [64][68]  Qt[d][r]
    float* Kt = Qt + 64 * 68;       // [64][68]  Kt[d][c]
    float* Pt = Kt + 64 * 68;       // [64][68]  Pt[c][r]
    float* Vs = Pt + 64 * 68;       // [64][64]  Vs[j][dd]

    const int tid = threadIdx.x;
    const int tx = tid & 15;
    const int ty = tid >> 4;
    const int qt = blockIdx.x;
    const int h  = blockIdx.y;
    const int b  = blockIdx.z;
    const int bh = b * HH + h;

    // Load Q tile (4096 contiguous floats), scatter transposed.
    const float4* Qg = (const float4*)(Q + ((size_t)bh * SS + qt * 64) * HD);
#pragma unroll
    for (int k = 0; k < 4; ++k) {
        int fidx = tid + k * 256;        // 0..1023
        int r = fidx >> 4;
        int d4 = (fidx & 15) * 4;
        float4 v = Qg[fidx];
        Qt[(d4 + 0) * 68 + r] = v.x;
        Qt[(d4 + 1) * 68 + r] = v.y;
        Qt[(d4 + 2) * 68 + r] = v.z;
        Qt[(d4 + 3) * 68 + r] = v.w;
    }

    float m_r[4], l_r[4], o_r[4][4];
#pragma unroll
    for (int i = 0; i < 4; ++i) {
        m_r[i] = -INFINITY;
        l_r[i] = 0.0f;
#pragma unroll
        for (int j = 0; j < 4; ++j) o_r[i][j] = 0.0f;
    }

    const float scale = 0.125f;  // 1/sqrt(64)

    for (int kt = 0; kt <= qt; ++kt) {
        __syncthreads();  // prior-iteration consumers done (also orders Q load once)

        const float4* Kg = (const float4*)(K + ((size_t)bh * SS + kt * 64) * HD);
        const float4* Vg = (const float4*)(V + ((size_t)bh * SS + kt * 64) * HD);
#pragma unroll
        for (int k = 0; k < 4; ++k) {
            int fidx = tid + k * 256;
            int r = fidx >> 4;
            int d4 = (fidx & 15) * 4;
            float4 v = Kg[fidx];
            Kt[(d4 + 0) * 68 + r] = v.x;
            Kt[(d4 + 1) * 68 + r] = v.y;
            Kt[(d4 + 2) * 68 + r] = v.z;
            Kt[(d4 + 3) * 68 + r] = v.w;
            ((float4*)Vs)[fidx] = Vg[fidx];
        }
        __syncthreads();

        // S = Q K^T (64x64, 4x4 per thread)
        float s[4][4];
#pragma unroll
        for (int i = 0; i < 4; ++i)
#pragma unroll
            for (int j = 0; j < 4; ++j) s[i][j] = 0.0f;

#pragma unroll 16
        for (int d = 0; d < 64; ++d) {
            float4 qv = *(const float4*)&Qt[d * 68 + ty * 4];
            float4 kv = *(const float4*)&Kt[d * 68 + tx * 4];
            s[0][0] = fmaf(qv.x, kv.x, s[0][0]);
            s[0][1] = fmaf(qv.x, kv.y, s[0][1]);
            s[0][2] = fmaf(qv.x, kv.z, s[0][2]);
            s[0][3] = fmaf(qv.x, kv.w, s[0][3]);
            s[1][0] = fmaf(qv.y, kv.x, s[1][0]);
            s[1][1] = fmaf(qv.y, kv.y, s[1][1]);
            s[1][2] = fmaf(qv.y, kv.z, s[1][2]);
            s[1][3] = fmaf(qv.y, kv.w, s[1][3]);
            s[2][0] = fmaf(qv.z, kv.x, s[2][0]);
            s[2][1] = fmaf(qv.z, kv.y, s[2][1]);
            s[2][2] = fmaf(qv.z, kv.z, s[2][2]);
            s[2][3] = fmaf(qv.z, kv.w, s[2][3]);
            s[3][0] = fmaf(qv.w, kv.x, s[3][0]);
            s[3][1] = fmaf(qv.w, kv.y, s[3][1]);
            s[3][2] = fmaf(qv.w, kv.z, s[3][2]);
            s[3][3] = fmaf(qv.w, kv.w, s[3][3]);
        }

        const bool diag = (kt == qt);
#pragma unroll
        for (int i = 0; i < 4; ++i)
#pragma unroll
            for (int j = 0; j < 4; ++j) {
                float v = s[i][j] * scale;
                if (diag && (tx * 4 + j > ty * 4 + i)) v = -1.0e30f;
                s[i][j] = v;
            }

        // online softmax per row (reduce over 16 lanes of the row group)
#pragma unroll
        for (int i = 0; i < 4; ++i) {
            float mx = fmaxf(fmaxf(s[i][0], s[i][1]), fmaxf(s[i][2], s[i][3]));
#pragma unroll
            for (int off = 8; off >= 1; off >>= 1)
                mx = fmaxf(mx, __shfl_xor_sync(0xffffffffu, mx, off));
            float mnew = fmaxf(m_r[i], mx);
            float corr = __expf(m_r[i] - mnew);
            m_r[i] = mnew;
            float rs = 0.0f;
#pragma unroll
            for (int j = 0; j < 4; ++j) {
                s[i][j] = __expf(s[i][j] - mnew);
                rs += s[i][j];
            }
#pragma unroll
            for (int off = 8; off >= 1; off >>= 1)
                rs += __shfl_xor_sync(0xffffffffu, rs, off);
            l_r[i] = l_r[i] * corr + rs;
            o_r[i][0] *= corr;
            o_r[i][1] *= corr;
            o_r[i][2] *= corr;
            o_r[i][3] *= corr;
        }

        // write P transposed: Pt[c][r]
#pragma unroll
        for (int i = 0; i < 4; ++i)
#pragma unroll
            for (int j = 0; j < 4; ++j)
                Pt[(tx * 4 + j) * 68 + (ty * 4 + i)] = s[i][j];
        __syncthreads();

        // O += P V
#pragma unroll 16
        for (int j = 0; j < 64; ++j) {
            float4 pv = *(const float4*)&Pt[j * 68 + ty * 4];
            float4 vv = *(const float4*)&Vs[j * 64 + tx * 4];
            o_r[0][0] = fmaf(pv.x, vv.x, o_r[0][0]);
            o_r[0][1] = fmaf(pv.x, vv.y, o_r[0][1]);
            o_r[0][2] = fmaf(pv.x, vv.z, o_r[0][2]);
            o_r[0][3] = fmaf(pv.x, vv.w, o_r[0][3]);
            o_r[1][0] = fmaf(pv.y, vv.x, o_r[1][0]);
            o_r[1][1] = fmaf(pv.y, vv.y, o_r[1][1]);
            o_r[1][2] = fmaf(pv.y, vv.z, o_r[1][2]);
            o_r[1][3] = fmaf(pv.y, vv.w, o_r[1][3]);
            o_r[2][0] = fmaf(pv.z, vv.x, o_r[2][0]);
            o_r[2][1] = fmaf(pv.z, vv.y, o_r[2][1]);
            o_r[2][2] = fmaf(pv.z, vv.z, o_r[2][2]);
            o_r[2][3] = fmaf(pv.z, vv.w, o_r[2][3]);
            o_r[3][0] = fmaf(pv.w, vv.x, o_r[3][0]);
            o_r[3][1] = fmaf(pv.w, vv.y, o_r[3][1]);
            o_r[3][2] = fmaf(pv.w, vv.z, o_r[3][2]);
            o_r[3][3] = fmaf(pv.w, vv.w, o_r[3][3]);
        }
    }

    // epilogue: ctx[b][q][h*64 + dd] = o / l
    float* Og = O + ((size_t)b * SS + qt * 64) * DD + h * HD;
#pragma unroll
    for (int i = 0; i < 4; ++i) {
        float inv = 1.0f / l_r[i];
        float4 out;
        out.x = o_r[i][0] * inv;
        out.y = o_r[i][1] * inv;
        out.z = o_r[i][2] * inv;
        out.w = o_r[i][3] * inv;
        *(float4*)&Og[(size_t)(ty * 4 + i) * DD + tx * 4] = out;
    }
}

// ---------------------------------------------------------------------------
// kernel_launch
// Input order: x, mask, rope_cos, rope_sin, Wq, bq, Wk, bk, Wv, bv, Wo, bo
// ---------------------------------------------------------------------------
extern "C" void kernel_launch(void* const* d_in, const int* in_sizes, int n_in,
                              void* d_out, int out_size)
{
    (void)in_sizes; (void)n_in; (void)out_size;

    const float* x    = (const float*)d_in[0];
    const float* cosb = (const float*)d_in[2];
    const float* sinb = (const float*)d_in[3];
    const float* Wq = (const float*)d_in[4];
    const float* bq = (const float*)d_in[5];
    const float* Wk = (const float*)d_in[6];
    const float* bk = (const float*)d_in[7];
    const float* Wv = (const float*)d_in[8];
    const float* bv = (const float*)d_in[9];
    const float* Wo = (const float*)d_in[10];
    const float* bo = (const float*)d_in[11];
    float* out = (float*)d_out;

    float *Qp, *Kp, *Vp, *Cp;
    cudaGetSymbolAddress((void**)&Qp, g_Q);
    cudaGetSymbolAddress((void**)&Kp, g_K);
    cudaGetSymbolAddress((void**)&Vp, g_V);
    cudaGetSymbolAddress((void**)&Cp, g_ctx);

    dim3 ggrid(DD / 64, MROWS / 64);  // (16, 128)

    gemm_bias_kernel<true><<<ggrid, 256>>>(x, Wq, bq, Qp);
    gemm_bias_kernel<true><<<ggrid, 256>>>(x, Wk, bk, Kp);
    gemm_bias_kernel<true><<<ggrid, 256>>>(x, Wv, bv, Vp);

    int rope_threads = BB * HH * SS * 32;  // 4,194,304
    rope_kernel<<<rope_threads / 256, 256>>>(Qp, cosb, sinb);
    rope_kernel<<<rope_threads / 256, 256>>>(Kp, cosb, sinb);

    cudaFuncSetAttribute(flash_kernel,
                         cudaFuncAttributeMaxDynamicSharedMemorySize,
                         FLASH_SMEM_BYTES);
    flash_kernel<<<dim3(SS / 64, HH, BB), 256, FLASH_SMEM_BYTES>>>(Qp, Kp, Vp, Cp);

    gemm_bias_kernel<false><<<ggrid, 256>>>(Cp, Wo, bo, out);
}

// round 4
// speedup vs baseline: 1.7540x; 1.7540x over previous
#include <cuda_runtime.h>
#include <math.h>
#include <stdint.h>

// Problem constants
#define BB 4
#define HH 16
#define SS 2048
#define DD 1024
#define HD 64
#define MROWS (BB * SS)   // 8192

// ---------------------------------------------------------------------------
// Scratch (no allocations allowed -> __device__ globals)
// ---------------------------------------------------------------------------
__device__ float g_Q[BB * HH * SS * HD];
__device__ float g_K[BB * HH * SS * HD];
__device__ float g_V[BB * HH * SS * HD];
__device__ float g_ctx[BB * SS * DD];

// ---------------------------------------------------------------------------
// helpers
// ---------------------------------------------------------------------------
__device__ __forceinline__ uint32_t smem_u32(const void* p) {
    uint32_t a;
    asm("{ .reg .u64 t; cvta.to.shared.u64 t, %1; cvt.u32.u64 %0, t; }"
        : "=r"(a) : "l"(p));
    return a;
}

__device__ __forceinline__ uint32_t f2tf32(float f) {
    uint32_t u;
    asm("cvt.rna.tf32.f32 %0, %1;" : "=r"(u) : "f"(f));
    return u;
}

// mma.sync m16n8k8 tf32, fp32 accumulate (in place on d)
__device__ __forceinline__ void mma_tf32(float d[4], const uint32_t a[4],
                                         const uint32_t b[2]) {
    asm volatile(
        "mma.sync.aligned.m16n8k8.row.col.f32.tf32.tf32.f32 "
        "{%0,%1,%2,%3}, {%4,%5,%6,%7}, {%8,%9}, {%0,%1,%2,%3};"
        : "+f"(d[0]), "+f"(d[1]), "+f"(d[2]), "+f"(d[3])
        : "r"(a[0]), "r"(a[1]), "r"(a[2]), "r"(a[3]), "r"(b[0]), "r"(b[1]));
}

// ===========================================================================
// tf32 mma.sync GEMM: Y[m][n] = sum_k X[m][k]*W[n][k] + bias[n]
// M=8192, N=1024, K=1024. CTA tile 128x128, BK=32.
// 8 warps as 4(m) x 2(n); warp tile 32x64 = 2 m16 x 8 n8 tiles.
// 3-stage cp.async ring. Smem padded to 36 floats/row (conflict-free frags).
// ===========================================================================
#define GBK 32
#define GPAD 36
#define GSTAGE_FLOATS (128 * GPAD)            // per matrix per stage = 4608
#define GSTAGE_BYTES  (2 * GSTAGE_FLOATS * 4) // 36864
#define GNSTAGE 3
#define GEMM_SMEM (GNSTAGE * GSTAGE_BYTES)    // 110592

__device__ __forceinline__ void gemm_issue_loads(
    const float* __restrict__ X, const float* __restrict__ W,
    int m0, int n0, int tid, uint32_t stage_addr, int k0)
{
    // A: 128 rows x 32 floats (8 x 16B chunks per row), padded stride 144B
#pragma unroll
    for (int t = 0; t < 4; ++t) {
        int idx = tid + t * 256;
        int row = idx >> 3;
        int c = idx & 7;
        const float* src = X + (size_t)(m0 + row) * 1024 + k0 + c * 4;
        uint32_t dst = stage_addr + row * 144 + c * 16;
        asm volatile("cp.async.cg.shared.global [%0], [%1], 16;"
                     :: "r"(dst), "l"(src));
    }
    // B: 128 rows (n) x 32 floats
#pragma unroll
    for (int t = 0; t < 4; ++t) {
        int idx = tid + t * 256;
        int row = idx >> 3;
        int c = idx & 7;
        const float* src = W + (size_t)(n0 + row) * 1024 + k0 + c * 4;
        uint32_t dst = stage_addr + 18432 + row * 144 + c * 16;
        asm volatile("cp.async.cg.shared.global [%0], [%1], 16;"
                     :: "r"(dst), "l"(src));
    }
}

template <bool BHSD>
__global__ __launch_bounds__(256)
void gemm_mma_kernel(const float* __restrict__ X, const float* __restrict__ W,
                     const float* __restrict__ bias, float* __restrict__ Y)
{
    extern __shared__ __align__(16) float smem[];
    const uint32_t sb = smem_u32(smem);
    const int tid = threadIdx.x;
    const int wid = tid >> 5;
    const int lane = tid & 31;
    const int wm = wid >> 1;        // 0..3
    const int wn = wid & 1;         // 0..1
    const int m0 = blockIdx.y * 128;
    const int n0 = blockIdx.x * 128;

    const int lr = lane >> 2;       // 0..7
    const int lc = lane & 3;        // 0..3

    float acc[2][8][4];
#pragma unroll
    for (int mt = 0; mt < 2; ++mt)
#pragma unroll
        for (int nt = 0; nt < 8; ++nt)
#pragma unroll
            for (int i = 0; i < 4; ++i) acc[mt][nt][i] = 0.0f;

    // prologue
    gemm_issue_loads(X, W, m0, n0, tid, sb + 0 * GSTAGE_BYTES, 0);
    asm volatile("cp.async.commit_group;" ::: "memory");
    gemm_issue_loads(X, W, m0, n0, tid, sb + 1 * GSTAGE_BYTES, GBK);
    asm volatile("cp.async.commit_group;" ::: "memory");

    const int NK = 1024 / GBK;   // 32
    for (int s = 0; s < NK; ++s) {
        int t = s + 2;
        if (t < NK)
            gemm_issue_loads(X, W, m0, n0, tid,
                             sb + (t % GNSTAGE) * GSTAGE_BYTES, t * GBK);
        asm volatile("cp.async.commit_group;" ::: "memory");
        asm volatile("cp.async.wait_group 2;" ::: "memory");
        __syncthreads();

        const float* As = smem + (s % GNSTAGE) * (2 * GSTAGE_FLOATS);
        const float* Bs = As + GSTAGE_FLOATS;

#pragma unroll
        for (int kk = 0; kk < 4; ++kk) {
            int k0 = kk * 8 + lc;
            uint32_t af[2][4];
#pragma unroll
            for (int mt = 0; mt < 2; ++mt) {
                int r = wm * 32 + mt * 16 + lr;
                af[mt][0] = f2tf32(As[r * GPAD + k0]);
                af[mt][1] = f2tf32(As[(r + 8) * GPAD + k0]);
                af[mt][2] = f2tf32(As[r * GPAD + k0 + 4]);
                af[mt][3] = f2tf32(As[(r + 8) * GPAD + k0 + 4]);
            }
            uint32_t bf[8][2];
#pragma unroll
            for (int nt = 0; nt < 8; ++nt) {
                int n = wn * 64 + nt * 8 + lr;
                bf[nt][0] = f2tf32(Bs[n * GPAD + k0]);
                bf[nt][1] = f2tf32(Bs[n * GPAD + k0 + 4]);
            }
#pragma unroll
            for (int mt = 0; mt < 2; ++mt)
#pragma unroll
                for (int nt = 0; nt < 8; ++nt)
                    mma_tf32(acc[mt][nt], af[mt], bf[nt]);
        }
        __syncthreads();
    }

    // epilogue: direct float2 stores with bias
#pragma unroll
    for (int nt = 0; nt < 8; ++nt) {
        int ncol = n0 + wn * 64 + nt * 8 + 2 * lc;
        float b0 = __ldg(&bias[ncol]);
        float b1 = __ldg(&bias[ncol + 1]);
#pragma unroll
        for (int mt = 0; mt < 2; ++mt) {
            int m = m0 + wm * 32 + mt * 16 + lr;
            float2 v0 = make_float2(acc[mt][nt][0] + b0, acc[mt][nt][1] + b1);
            float2 v1 = make_float2(acc[mt][nt][2] + b0, acc[mt][nt][3] + b1);
            if (BHSD) {
                int b   = m >> 11;
                int sq  = m & 2047;
                int h   = ncol >> 6;
                int dd  = ncol & 63;
                float* d0 = &Y[(((size_t)(b * HH + h) * SS) + sq) * HD + dd];
                *(float2*)d0 = v0;
                int m8 = m + 8;
                int b8 = m8 >> 11;
                int sq8 = m8 & 2047;
                float* d1 = &Y[(((size_t)(b8 * HH + h) * SS) + sq8) * HD + dd];
                *(float2*)d1 = v1;
            } else {
                *(float2*)&Y[(size_t)m * DD + ncol] = v0;
                *(float2*)&Y[(size_t)(m + 8) * DD + ncol] = v1;
            }
        }
    }
}

// ---------------------------------------------------------------------------
// RoPE in-place on [B, H, S, 64]. One thread handles an (i, i+32) pair.
// ---------------------------------------------------------------------------
__global__ void rope_kernel(float* __restrict__ P,
                            const float* __restrict__ cosb,
                            const float* __restrict__ sinb)
{
    int idx = blockIdx.x * blockDim.x + threadIdx.x; // < B*H*S*32
    int i = idx & 31;
    int bhs = idx >> 5;
    int s = bhs & (SS - 1);
    float* p = P + (size_t)bhs * HD;
    float x0 = p[i];
    float x1 = p[i + 32];
    float c  = cosb[s * HD + i];
    float sn = sinb[s * HD + i];
    p[i]      = x0 * c - x1 * sn;
    p[i + 32] = x1 * c + x0 * sn;
}

// ---------------------------------------------------------------------------
// Causal flash attention, fp32. Block: 256 threads (16x16), BM=BN=64, HD=64.
// ---------------------------------------------------------------------------
#define FLASH_SMEM_FLOATS (3 * 64 * 68 + 64 * 64)
#define FLASH_SMEM_BYTES  (FLASH_SMEM_FLOATS * 4)

__global__ __launch_bounds__(256) void flash_kernel(
    const float* __restrict__ Q, const float* __restrict__ K,
    const float* __restrict__ V, float* __restrict__ O)
{
    extern __shared__ __align__(16) float sm[];
    float* Qt = sm;                 // [64][68]  Qt[d][r]
    float* Kt = Qt + 64 * 68;       // [64][68]  Kt[d][c]
    float* Pt = Kt + 64 * 68;       // [64][68]  Pt[c][r]
    float* Vs = Pt + 64 * 68;       // [64][64]  Vs[j][dd]

    const int tid = threadIdx.x;
    const int tx = tid & 15;
    const int ty = tid >> 4;
    const int qt = blockIdx.x;
    const int h  = blockIdx.y;
    const int b  = blockIdx.z;
    const int bh = b * HH + h;

    const float4* Qg = (const float4*)(Q + ((size_t)bh * SS + qt * 64) * HD);
#pragma unroll
    for (int k = 0; k < 4; ++k) {
        int fidx = tid + k * 256;
        int r = fidx >> 4;
        int d4 = (fidx & 15) * 4;
        float4 v = Qg[fidx];
        Qt[(d4 + 0) * 68 + r] = v.x;
        Qt[(d4 + 1) * 68 + r] = v.y;
        Qt[(d4 + 2) * 68 + r] = v.z;
        Qt[(d4 + 3) * 68 + r] = v.w;
    }

    float m_r[4], l_r[4], o_r[4][4];
#pragma unroll
    for (int i = 0; i < 4; ++i) {
        m_r[i] = -INFINITY;
        l_r[i] = 0.0f;
#pragma unroll
        for (int j = 0; j < 4; ++j) o_r[i][j] = 0.0f;
    }

    const float scale = 0.125f;

    for (int kt = 0; kt <= qt; ++kt) {
        __syncthreads();

        const float4* Kg = (const float4*)(K + ((size_t)bh * SS + kt * 64) * HD);
        const float4* Vg = (const float4*)(V + ((size_t)bh * SS + kt * 64) * HD);
#pragma unroll
        for (int k = 0; k < 4; ++k) {
            int fidx = tid + k * 256;
            int r = fidx >> 4;
            int d4 = (fidx & 15) * 4;
            float4 v = Kg[fidx];
            Kt[(d4 + 0) * 68 + r] = v.x;
            Kt[(d4 + 1) * 68 + r] = v.y;
            Kt[(d4 + 2) * 68 + r] = v.z;
            Kt[(d4 + 3) * 68 + r] = v.w;
            ((float4*)Vs)[fidx] = Vg[fidx];
        }
        __syncthreads();

        float s[4][4];
#pragma unroll
        for (int i = 0; i < 4; ++i)
#pragma unroll
            for (int j = 0; j < 4; ++j) s[i][j] = 0.0f;

#pragma unroll 16
        for (int d = 0; d < 64; ++d) {
            float4 qv = *(const float4*)&Qt[d * 68 + ty * 4];
            float4 kv = *(const float4*)&Kt[d * 68 + tx * 4];
            s[0][0] = fmaf(qv.x, kv.x, s[0][0]);
            s[0][1] = fmaf(qv.x, kv.y, s[0][1]);
            s[0][2] = fmaf(qv.x, kv.z, s[0][2]);
            s[0][3] = fmaf(qv.x, kv.w, s[0][3]);
            s[1][0] = fmaf(qv.y, kv.x, s[1][0]);
            s[1][1] = fmaf(qv.y, kv.y, s[1][1]);
            s[1][2] = fmaf(qv.y, kv.z, s[1][2]);
            s[1][3] = fmaf(qv.y, kv.w, s[1][3]);
            s[2][0] = fmaf(qv.z, kv.x, s[2][0]);
            s[2][1] = fmaf(qv.z, kv.y, s[2][1]);
            s[2][2] = fmaf(qv.z, kv.z, s[2][2]);
            s[2][3] = fmaf(qv.z, kv.w, s[2][3]);
            s[3][0] = fmaf(qv.w, kv.x, s[3][0]);
            s[3][1] = fmaf(qv.w, kv.y, s[3][1]);
            s[3][2] = fmaf(qv.w, kv.z, s[3][2]);
            s[3][3] = fmaf(qv.w, kv.w, s[3][3]);
        }

        const bool diag = (kt == qt);
#pragma unroll
        for (int i = 0; i < 4; ++i)
#pragma unroll
            for (int j = 0; j < 4; ++j) {
                float v = s[i][j] * scale;
                if (diag && (tx * 4 + j > ty * 4 + i)) v = -1.0e30f;
                s[i][j] = v;
            }

#pragma unroll
        for (int i = 0; i < 4; ++i) {
            float mx = fmaxf(fmaxf(s[i][0], s[i][1]), fmaxf(s[i][2], s[i][3]));
#pragma unroll
            for (int off = 8; off >= 1; off >>= 1)
                mx = fmaxf(mx, __shfl_xor_sync(0xffffffffu, mx, off));
            float mnew = fmaxf(m_r[i], mx);
            float corr = __expf(m_r[i] - mnew);
            m_r[i] = mnew;
            float rs = 0.0f;
#pragma unroll
            for (int j = 0; j < 4; ++j) {
                s[i][j] = __expf(s[i][j] - mnew);
                rs += s[i][j];
            }
#pragma unroll
            for (int off = 8; off >= 1; off >>= 1)
                rs += __shfl_xor_sync(0xffffffffu, rs, off);
            l_r[i] = l_r[i] * corr + rs;
            o_r[i][0] *= corr;
            o_r[i][1] *= corr;
            o_r[i][2] *= corr;
            o_r[i][3] *= corr;
        }

#pragma unroll
        for (int i = 0; i < 4; ++i)
#pragma unroll
            for (int j = 0; j < 4; ++j)
                Pt[(tx * 4 + j) * 68 + (ty * 4 + i)] = s[i][j];
        __syncthreads();

#pragma unroll 16
        for (int j = 0; j < 64; ++j) {
            float4 pv = *(const float4*)&Pt[j * 68 + ty * 4];
            float4 vv = *(const float4*)&Vs[j * 64 + tx * 4];
            o_r[0][0] = fmaf(pv.x, vv.x, o_r[0][0]);
            o_r[0][1] = fmaf(pv.x, vv.y, o_r[0][1]);
            o_r[0][2] = fmaf(pv.x, vv.z, o_r[0][2]);
            o_r[0][3] = fmaf(pv.x, vv.w, o_r[0][3]);
            o_r[1][0] = fmaf(pv.y, vv.x, o_r[1][0]);
            o_r[1][1] = fmaf(pv.y, vv.y, o_r[1][1]);
            o_r[1][2] = fmaf(pv.y, vv.z, o_r[1][2]);
            o_r[1][3] = fmaf(pv.y, vv.w, o_r[1][3]);
            o_r[2][0] = fmaf(pv.z, vv.x, o_r[2][0]);
            o_r[2][1] = fmaf(pv.z, vv.y, o_r[2][1]);
            o_r[2][2] = fmaf(pv.z, vv.z, o_r[2][2]);
            o_r[2][3] = fmaf(pv.z, vv.w, o_r[2][3]);
            o_r[3][0] = fmaf(pv.w, vv.x, o_r[3][0]);
            o_r[3][1] = fmaf(pv.w, vv.y, o_r[3][1]);
            o_r[3][2] = fmaf(pv.w, vv.z, o_r[3][2]);
            o_r[3][3] = fmaf(pv.w, vv.w, o_r[3][3]);
        }
    }

    float* Og = O + ((size_t)b * SS + qt * 64) * DD + h * HD;
#pragma unroll
    for (int i = 0; i < 4; ++i) {
        float inv = 1.0f / l_r[i];
        float4 out;
        out.x = o_r[i][0] * inv;
        out.y = o_r[i][1] * inv;
        out.z = o_r[i][2] * inv;
        out.w = o_r[i][3] * inv;
        *(float4*)&Og[(size_t)(ty * 4 + i) * DD + tx * 4] = out;
    }
}

// ---------------------------------------------------------------------------
// kernel_launch
// Input order: x, mask, rope_cos, rope_sin, Wq, bq, Wk, bk, Wv, bv, Wo, bo
// ---------------------------------------------------------------------------
extern "C" void kernel_launch(void* const* d_in, const int* in_sizes, int n_in,
                              void* d_out, int out_size)
{
    (void)in_sizes; (void)n_in; (void)out_size;

    const float* x    = (const float*)d_in[0];
    const float* cosb = (const float*)d_in[2];
    const float* sinb = (const float*)d_in[3];
    const float* Wq = (const float*)d_in[4];
    const float* bq = (const float*)d_in[5];
    const float* Wk = (const float*)d_in[6];
    const float* bk = (const float*)d_in[7];
    const float* Wv = (const float*)d_in[8];
    const float* bv = (const float*)d_in[9];
    const float* Wo = (const float*)d_in[10];
    const float* bo = (const float*)d_in[11];
    float* out = (float*)d_out;

    float *Qp, *Kp, *Vp, *Cp;
    cudaGetSymbolAddress((void**)&Qp, g_Q);
    cudaGetSymbolAddress((void**)&Kp, g_K);
    cudaGetSymbolAddress((void**)&Vp, g_V);
    cudaGetSymbolAddress((void**)&Cp, g_ctx);

    cudaFuncSetAttribute(gemm_mma_kernel<true>,
                         cudaFuncAttributeMaxDynamicSharedMemorySize, GEMM_SMEM);
    cudaFuncSetAttribute(gemm_mma_kernel<false>,
                         cudaFuncAttributeMaxDynamicSharedMemorySize, GEMM_SMEM);

    dim3 ggrid(DD / 128, MROWS / 128);   // (8, 64) = 512 CTAs

    gemm_mma_kernel<true><<<ggrid, 256, GEMM_SMEM>>>(x, Wq, bq, Qp);
    gemm_mma_kernel<true><<<ggrid, 256, GEMM_SMEM>>>(x, Wk, bk, Kp);
    gemm_mma_kernel<true><<<ggrid, 256, GEMM_SMEM>>>(x, Wv, bv, Vp);

    int rope_threads = BB * HH * SS * 32;
    rope_kernel<<<rope_threads / 256, 256>>>(Qp, cosb, sinb);
    rope_kernel<<<rope_threads / 256, 256>>>(Kp, cosb, sinb);

    cudaFuncSetAttribute(flash_kernel,
                         cudaFuncAttributeMaxDynamicSharedMemorySize,
                         FLASH_SMEM_BYTES);
    flash_kernel<<<dim3(SS / 64, HH, BB), 256, FLASH_SMEM_BYTES>>>(Qp, Kp, Vp, Cp);

    gemm_mma_kernel<false><<<ggrid, 256, GEMM_SMEM>>>(Cp, Wo, bo, out);
}

// round 5
// speedup vs baseline: 3.0138x; 1.7182x over previous
#include <cuda_runtime.h>
#include <math.h>
#include <stdint.h>

// Problem constants
#define BB 4
#define HH 16
#define SS 2048
#define DD 1024
#define HD 64
#define MROWS (BB * SS)   // 8192

// ---------------------------------------------------------------------------
// Scratch (no allocations allowed -> __device__ globals)
// ---------------------------------------------------------------------------
__device__ float g_Q[BB * HH * SS * HD];
__device__ float g_K[BB * HH * SS * HD];
__device__ float g_V[BB * HH * SS * HD];
__device__ float g_ctx[BB * SS * DD];

// ---------------------------------------------------------------------------
// helpers
// ---------------------------------------------------------------------------
__device__ __forceinline__ uint32_t smem_u32(const void* p) {
    uint32_t a;
    asm("{ .reg .u64 t; cvta.to.shared.u64 t, %1; cvt.u32.u64 %0, t; }"
        : "=r"(a) : "l"(p));
    return a;
}

__device__ __forceinline__ uint32_t f2tf32(float f) {
    uint32_t u;
    asm("cvt.rna.tf32.f32 %0, %1;" : "=r"(u) : "f"(f));
    return u;
}

// mma.sync m16n8k8 tf32, fp32 accumulate (in place on d)
__device__ __forceinline__ void mma_tf32(float d[4], const uint32_t a[4],
                                         const uint32_t b[2]) {
    asm volatile(
        "mma.sync.aligned.m16n8k8.row.col.f32.tf32.tf32.f32 "
        "{%0,%1,%2,%3}, {%4,%5,%6,%7}, {%8,%9}, {%0,%1,%2,%3};"
        : "+f"(d[0]), "+f"(d[1]), "+f"(d[2]), "+f"(d[3])
        : "r"(a[0]), "r"(a[1]), "r"(a[2]), "r"(a[3]), "r"(b[0]), "r"(b[1]));
}

// ===========================================================================
// tf32 mma.sync GEMM: Y[m][n] = sum_k X[m][k]*W[n][k] + bias[n]
// (unchanged from Round 4 - verified)
// ===========================================================================
#define GBK 32
#define GPAD 36
#define GSTAGE_FLOATS (128 * GPAD)
#define GSTAGE_BYTES  (2 * GSTAGE_FLOATS * 4)
#define GNSTAGE 3
#define GEMM_SMEM (GNSTAGE * GSTAGE_BYTES)

__device__ __forceinline__ void gemm_issue_loads(
    const float* __restrict__ X, const float* __restrict__ W,
    int m0, int n0, int tid, uint32_t stage_addr, int k0)
{
#pragma unroll
    for (int t = 0; t < 4; ++t) {
        int idx = tid + t * 256;
        int row = idx >> 3;
        int c = idx & 7;
        const float* src = X + (size_t)(m0 + row) * 1024 + k0 + c * 4;
        uint32_t dst = stage_addr + row * 144 + c * 16;
        asm volatile("cp.async.cg.shared.global [%0], [%1], 16;"
                     :: "r"(dst), "l"(src));
    }
#pragma unroll
    for (int t = 0; t < 4; ++t) {
        int idx = tid + t * 256;
        int row = idx >> 3;
        int c = idx & 7;
        const float* src = W + (size_t)(n0 + row) * 1024 + k0 + c * 4;
        uint32_t dst = stage_addr + 18432 + row * 144 + c * 16;
        asm volatile("cp.async.cg.shared.global [%0], [%1], 16;"
                     :: "r"(dst), "l"(src));
    }
}

template <bool BHSD>
__global__ __launch_bounds__(256)
void gemm_mma_kernel(const float* __restrict__ X, const float* __restrict__ W,
                     const float* __restrict__ bias, float* __restrict__ Y)
{
    extern __shared__ __align__(16) float smem[];
    const uint32_t sb = smem_u32(smem);
    const int tid = threadIdx.x;
    const int wid = tid >> 5;
    const int lane = tid & 31;
    const int wm = wid >> 1;
    const int wn = wid & 1;
    const int m0 = blockIdx.y * 128;
    const int n0 = blockIdx.x * 128;

    const int lr = lane >> 2;
    const int lc = lane & 3;

    float acc[2][8][4];
#pragma unroll
    for (int mt = 0; mt < 2; ++mt)
#pragma unroll
        for (int nt = 0; nt < 8; ++nt)
#pragma unroll
            for (int i = 0; i < 4; ++i) acc[mt][nt][i] = 0.0f;

    gemm_issue_loads(X, W, m0, n0, tid, sb + 0 * GSTAGE_BYTES, 0);
    asm volatile("cp.async.commit_group;" ::: "memory");
    gemm_issue_loads(X, W, m0, n0, tid, sb + 1 * GSTAGE_BYTES, GBK);
    asm volatile("cp.async.commit_group;" ::: "memory");

    const int NK = 1024 / GBK;
    for (int s = 0; s < NK; ++s) {
        int t = s + 2;
        if (t < NK)
            gemm_issue_loads(X, W, m0, n0, tid,
                             sb + (t % GNSTAGE) * GSTAGE_BYTES, t * GBK);
        asm volatile("cp.async.commit_group;" ::: "memory");
        asm volatile("cp.async.wait_group 2;" ::: "memory");
        __syncthreads();

        const float* As = smem + (s % GNSTAGE) * (2 * GSTAGE_FLOATS);
        const float* Bs = As + GSTAGE_FLOATS;

#pragma unroll
        for (int kk = 0; kk < 4; ++kk) {
            int k0 = kk * 8 + lc;
            uint32_t af[2][4];
#pragma unroll
            for (int mt = 0; mt < 2; ++mt) {
                int r = wm * 32 + mt * 16 + lr;
                af[mt][0] = f2tf32(As[r * GPAD + k0]);
                af[mt][1] = f2tf32(As[(r + 8) * GPAD + k0]);
                af[mt][2] = f2tf32(As[r * GPAD + k0 + 4]);
                af[mt][3] = f2tf32(As[(r + 8) * GPAD + k0 + 4]);
            }
            uint32_t bf[8][2];
#pragma unroll
            for (int nt = 0; nt < 8; ++nt) {
                int n = wn * 64 + nt * 8 + lr;
                bf[nt][0] = f2tf32(Bs[n * GPAD + k0]);
                bf[nt][1] = f2tf32(Bs[n * GPAD + k0 + 4]);
            }
#pragma unroll
            for (int mt = 0; mt < 2; ++mt)
#pragma unroll
                for (int nt = 0; nt < 8; ++nt)
                    mma_tf32(acc[mt][nt], af[mt], bf[nt]);
        }
        __syncthreads();
    }

#pragma unroll
    for (int nt = 0; nt < 8; ++nt) {
        int ncol = n0 + wn * 64 + nt * 8 + 2 * lc;
        float b0 = __ldg(&bias[ncol]);
        float b1 = __ldg(&bias[ncol + 1]);
#pragma unroll
        for (int mt = 0; mt < 2; ++mt) {
            int m = m0 + wm * 32 + mt * 16 + lr;
            float2 v0 = make_float2(acc[mt][nt][0] + b0, acc[mt][nt][1] + b1);
            float2 v1 = make_float2(acc[mt][nt][2] + b0, acc[mt][nt][3] + b1);
            if (BHSD) {
                int b   = m >> 11;
                int sq  = m & 2047;
                int h   = ncol >> 6;
                int dd  = ncol & 63;
                float* d0 = &Y[(((size_t)(b * HH + h) * SS) + sq) * HD + dd];
                *(float2*)d0 = v0;
                int m8 = m + 8;
                int b8 = m8 >> 11;
                int sq8 = m8 & 2047;
                float* d1 = &Y[(((size_t)(b8 * HH + h) * SS) + sq8) * HD + dd];
                *(float2*)d1 = v1;
            } else {
                *(float2*)&Y[(size_t)m * DD + ncol] = v0;
                *(float2*)&Y[(size_t)(m + 8) * DD + ncol] = v1;
            }
        }
    }
}

// ---------------------------------------------------------------------------
// RoPE in-place on [B, H, S, 64]. One thread handles an (i, i+32) pair.
// ---------------------------------------------------------------------------
__global__ void rope_kernel(float* __restrict__ P,
                            const float* __restrict__ cosb,
                            const float* __restrict__ sinb)
{
    int idx = blockIdx.x * blockDim.x + threadIdx.x;
    int i = idx & 31;
    int bhs = idx >> 5;
    int s = bhs & (SS - 1);
    float* p = P + (size_t)bhs * HD;
    float x0 = p[i];
    float x1 = p[i + 32];
    float c  = cosb[s * HD + i];
    float sn = sinb[s * HD + i];
    p[i]      = x0 * c - x1 * sn;
    p[i + 32] = x1 * c + x0 * sn;
}

// ===========================================================================
// Flash attention via mma.sync tf32.
// BM=128 (8 warps x 16 rows), BN=64 per iteration, HD=64.
// Smem: Ks[2][64][68], Vs[2][64][68] (double buffered), QP[128][68]
//   (Q staging at start, then reused for P tiles).
// Q fragments (scaled by 1/8, tf32) live in registers for the whole CTA.
// ===========================================================================
#define FPAD 68
#define F_KS0 0                       // floats
#define F_VS0 (2 * 64 * FPAD)         // 8704
#define F_QP  (4 * 64 * FPAD)         // 17408
#define FLASH_SMEM ((4 * 64 * FPAD + 128 * FPAD) * 4)   // 104448 bytes

__device__ __forceinline__ void flash_load_kv(
    const float* __restrict__ Kg, const float* __restrict__ Vg,
    int tid, uint32_t ks_addr, uint32_t vs_addr)
{
    // K tile: 64 rows x 64 floats = 1024 float4; 4 per thread. Same for V.
#pragma unroll
    for (int t = 0; t < 4; ++t) {
        int idx = tid + t * 256;
        int row = idx >> 4;
        int c4 = idx & 15;
        const float* srcK = Kg + row * HD + c4 * 4;
        const float* srcV = Vg + row * HD + c4 * 4;
        uint32_t dK = ks_addr + row * (FPAD * 4) + c4 * 16;
        uint32_t dV = vs_addr + row * (FPAD * 4) + c4 * 16;
        asm volatile("cp.async.cg.shared.global [%0], [%1], 16;" :: "r"(dK), "l"(srcK));
        asm volatile("cp.async.cg.shared.global [%0], [%1], 16;" :: "r"(dV), "l"(srcV));
    }
}

__global__ __launch_bounds__(256)
void flash_mma_kernel(const float* __restrict__ Q, const float* __restrict__ K,
                      const float* __restrict__ V, float* __restrict__ O)
{
    extern __shared__ __align__(16) float sm[];
    const uint32_t sb = smem_u32(sm);

    const int tid = threadIdx.x;
    const int w = tid >> 5;
    const int lane = tid & 31;
    const int lr = lane >> 2;       // 0..7
    const int lc = lane & 3;        // 0..3

    const int qt = (SS / 128 - 1) - blockIdx.x;   // big tiles first
    const int h  = blockIdx.y;
    const int b  = blockIdx.z;
    const int bh = b * HH + h;

    const float* Qg = Q + ((size_t)bh * SS + qt * 128) * HD;
    const float* Kb = K + (size_t)bh * SS * HD;
    const float* Vb = V + (size_t)bh * SS * HD;

    // ---- stage Q into smem (QP region), then extract scaled tf32 frags ----
    float* QP = sm + F_QP;
#pragma unroll
    for (int t = 0; t < 8; ++t) {
        int idx = tid + t * 256;     // 0..2047 float4
        int row = idx >> 4;
        int c4 = (idx & 15) * 4;
        float4 v = *(const float4*)(Qg + row * HD + c4);
        *(float4*)&QP[row * FPAD + c4] = v;
    }
    __syncthreads();

    uint32_t qa[8][4];
    {
        const float s8 = 0.125f;     // 1/sqrt(64) folded into Q
        int r = w * 16 + lr;
#pragma unroll
        for (int kk = 0; kk < 8; ++kk) {
            int k0 = kk * 8 + lc;
            qa[kk][0] = f2tf32(QP[r * FPAD + k0] * s8);
            qa[kk][1] = f2tf32(QP[(r + 8) * FPAD + k0] * s8);
            qa[kk][2] = f2tf32(QP[r * FPAD + k0 + 4] * s8);
            qa[kk][3] = f2tf32(QP[(r + 8) * FPAD + k0 + 4] * s8);
        }
    }
    // NOTE: QP becomes the P-staging region after the first __syncthreads in
    // the loop below.

    float oacc[8][4];
#pragma unroll
    for (int nt = 0; nt < 8; ++nt)
#pragma unroll
        for (int i = 0; i < 4; ++i) oacc[nt][i] = 0.0f;
    float mA = -INFINITY, mB = -INFINITY, lA = 0.0f, lB = 0.0f;

    const int jmax = 2 * qt + 1;

    // prologue: stage 0 loads
    flash_load_kv(Kb, Vb, tid,
                  sb + F_KS0 * 4, sb + F_VS0 * 4);
    asm volatile("cp.async.commit_group;" ::: "memory");

    float* Pt = QP;                  // P staging, warp-private rows

    for (int j = 0; j <= jmax; ++j) {
        __syncthreads();             // everyone done with stage j-1

        if (j + 1 <= jmax) {
            int st = (j + 1) & 1;
            flash_load_kv(Kb + (size_t)(j + 1) * 64 * HD,
                          Vb + (size_t)(j + 1) * 64 * HD, tid,
                          sb + (F_KS0 + st * 64 * FPAD) * 4,
                          sb + (F_VS0 + st * 64 * FPAD) * 4);
        }
        asm volatile("cp.async.commit_group;" ::: "memory");
        asm volatile("cp.async.wait_group 1;" ::: "memory");
        __syncthreads();             // stage j visible to all

        const int st = j & 1;
        const float* Ks = sm + F_KS0 + st * 64 * FPAD;
        const float* Vs = sm + F_VS0 + st * 64 * FPAD;

        // ---- S = (Q/8) K^T : 8 k-tiles x 8 n-tiles ----
        float sacc[8][4];
#pragma unroll
        for (int nt = 0; nt < 8; ++nt)
#pragma unroll
            for (int i = 0; i < 4; ++i) sacc[nt][i] = 0.0f;

#pragma unroll
        for (int kk = 0; kk < 8; ++kk) {
            int k0 = kk * 8 + lc;
#pragma unroll
            for (int nt = 0; nt < 8; ++nt) {
                int c = nt * 8 + lr;
                uint32_t bf[2];
                bf[0] = f2tf32(Ks[c * FPAD + k0]);
                bf[1] = f2tf32(Ks[c * FPAD + k0 + 4]);
                mma_tf32(sacc[nt], qa[kk], bf);
            }
        }

        // ---- causal mask (only last two j-blocks of this qt need it) ----
        if (j >= 2 * qt) {
            int rowA = qt * 128 + w * 16 + lr;
            int rowB = rowA + 8;
#pragma unroll
            for (int nt = 0; nt < 8; ++nt) {
                int c0 = j * 64 + nt * 8 + 2 * lc;
                int c1 = c0 + 1;
                if (c0 > rowA) sacc[nt][0] = -1.0e30f;
                if (c1 > rowA) sacc[nt][1] = -1.0e30f;
                if (c0 > rowB) sacc[nt][2] = -1.0e30f;
                if (c1 > rowB) sacc[nt][3] = -1.0e30f;
            }
        }

        // ---- online softmax (rows lr and lr+8 of this warp's 16) ----
        float mxA = -INFINITY, mxB = -INFINITY;
#pragma unroll
        for (int nt = 0; nt < 8; ++nt) {
            mxA = fmaxf(mxA, fmaxf(sacc[nt][0], sacc[nt][1]));
            mxB = fmaxf(mxB, fmaxf(sacc[nt][2], sacc[nt][3]));
        }
        mxA = fmaxf(mxA, __shfl_xor_sync(0xffffffffu, mxA, 1));
        mxA = fmaxf(mxA, __shfl_xor_sync(0xffffffffu, mxA, 2));
        mxB = fmaxf(mxB, __shfl_xor_sync(0xffffffffu, mxB, 1));
        mxB = fmaxf(mxB, __shfl_xor_sync(0xffffffffu, mxB, 2));

        float mnA = fmaxf(mA, mxA);
        float mnB = fmaxf(mB, mxB);
        float corrA = __expf(mA - mnA);
        float corrB = __expf(mB - mnB);
        mA = mnA; mB = mnB;

        float rsA = 0.0f, rsB = 0.0f;
#pragma unroll
        for (int nt = 0; nt < 8; ++nt) {
            sacc[nt][0] = __expf(sacc[nt][0] - mnA);
            sacc[nt][1] = __expf(sacc[nt][1] - mnA);
            sacc[nt][2] = __expf(sacc[nt][2] - mnB);
            sacc[nt][3] = __expf(sacc[nt][3] - mnB);
            rsA += sacc[nt][0] + sacc[nt][1];
            rsB += sacc[nt][2] + sacc[nt][3];
        }
        rsA += __shfl_xor_sync(0xffffffffu, rsA, 1);
        rsA += __shfl_xor_sync(0xffffffffu, rsA, 2);
        rsB += __shfl_xor_sync(0xffffffffu, rsB, 1);
        rsB += __shfl_xor_sync(0xffffffffu, rsB, 2);
        lA = lA * corrA + rsA;
        lB = lB * corrB + rsB;

#pragma unroll
        for (int nt = 0; nt < 8; ++nt) {
            oacc[nt][0] *= corrA;
            oacc[nt][1] *= corrA;
            oacc[nt][2] *= corrB;
            oacc[nt][3] *= corrB;
        }

        // ---- stage P (tf32 bits) into warp-private smem rows ----
        {
            int rA = w * 16 + lr;
#pragma unroll
            for (int nt = 0; nt < 8; ++nt) {
                int c = nt * 8 + 2 * lc;
                float2 pA, pB;
                pA.x = __uint_as_float(f2tf32(sacc[nt][0]));
                pA.y = __uint_as_float(f2tf32(sacc[nt][1]));
                pB.x = __uint_as_float(f2tf32(sacc[nt][2]));
                pB.y = __uint_as_float(f2tf32(sacc[nt][3]));
                *(float2*)&Pt[rA * FPAD + c] = pA;
                *(float2*)&Pt[(rA + 8) * FPAD + c] = pB;
            }
        }
        __syncwarp();

        // ---- O += P V ----
#pragma unroll
        for (int kk = 0; kk < 8; ++kk) {
            int k0 = kk * 8 + lc;
            int r = w * 16 + lr;
            uint32_t pa[4];
            pa[0] = __float_as_uint(Pt[r * FPAD + k0]);
            pa[1] = __float_as_uint(Pt[(r + 8) * FPAD + k0]);
            pa[2] = __float_as_uint(Pt[r * FPAD + k0 + 4]);
            pa[3] = __float_as_uint(Pt[(r + 8) * FPAD + k0 + 4]);
#pragma unroll
            for (int nt = 0; nt < 8; ++nt) {
                int d = nt * 8 + lr;
                uint32_t bf[2];
                bf[0] = f2tf32(Vs[(kk * 8 + lc) * FPAD + d]);
                bf[1] = f2tf32(Vs[(kk * 8 + lc + 4) * FPAD + d]);
                mma_tf32(oacc[nt], pa, bf);
            }
        }
        __syncwarp();   // Pt reads done before next iteration overwrites
    }

    // ---- epilogue: ctx[b][row][h*64 + d] = o / l ----
    float invA = 1.0f / lA;
    float invB = 1.0f / lB;
    int rowA = qt * 128 + w * 16 + lr;
    float* Og = O + ((size_t)b * SS) * DD + h * HD;
#pragma unroll
    for (int nt = 0; nt < 8; ++nt) {
        int d = nt * 8 + 2 * lc;
        float2 vA = make_float2(oacc[nt][0] * invA, oacc[nt][1] * invA);
        float2 vB = make_float2(oacc[nt][2] * invB, oacc[nt][3] * invB);
        *(float2*)&Og[(size_t)rowA * DD + d] = vA;
        *(float2*)&Og[(size_t)(rowA + 8) * DD + d] = vB;
    }
}

// ---------------------------------------------------------------------------
// kernel_launch
// Input order: x, mask, rope_cos, rope_sin, Wq, bq, Wk, bk, Wv, bv, Wo, bo
// ---------------------------------------------------------------------------
extern "C" void kernel_launch(void* const* d_in, const int* in_sizes, int n_in,
                              void* d_out, int out_size)
{
    (void)in_sizes; (void)n_in; (void)out_size;

    const float* x    = (const float*)d_in[0];
    const float* cosb = (const float*)d_in[2];
    const float* sinb = (const float*)d_in[3];
    const float* Wq = (const float*)d_in[4];
    const float* bq = (const float*)d_in[5];
    const float* Wk = (const float*)d_in[6];
    const float* bk = (const float*)d_in[7];
    const float* Wv = (const float*)d_in[8];
    const float* bv = (const float*)d_in[9];
    const float* Wo = (const float*)d_in[10];
    const float* bo = (const float*)d_in[11];
    float* out = (float*)d_out;

    float *Qp, *Kp, *Vp, *Cp;
    cudaGetSymbolAddress((void**)&Qp, g_Q);
    cudaGetSymbolAddress((void**)&Kp, g_K);
    cudaGetSymbolAddress((void**)&Vp, g_V);
    cudaGetSymbolAddress((void**)&Cp, g_ctx);

    cudaFuncSetAttribute(gemm_mma_kernel<true>,
                         cudaFuncAttributeMaxDynamicSharedMemorySize, GEMM_SMEM);
    cudaFuncSetAttribute(gemm_mma_kernel<false>,
                         cudaFuncAttributeMaxDynamicSharedMemorySize, GEMM_SMEM);
    cudaFuncSetAttribute(flash_mma_kernel,
                         cudaFuncAttributeMaxDynamicSharedMemorySize, FLASH_SMEM);

    dim3 ggrid(DD / 128, MROWS / 128);   // (8, 64) = 512 CTAs

    gemm_mma_kernel<true><<<ggrid, 256, GEMM_SMEM>>>(x, Wq, bq, Qp);
    gemm_mma_kernel<true><<<ggrid, 256, GEMM_SMEM>>>(x, Wk, bk, Kp);
    gemm_mma_kernel<true><<<ggrid, 256, GEMM_SMEM>>>(x, Wv, bv, Vp);

    int rope_threads = BB * HH * SS * 32;
    rope_kernel<<<rope_threads / 256, 256>>>(Qp, cosb, sinb);
    rope_kernel<<<rope_threads / 256, 256>>>(Kp, cosb, sinb);

    flash_mma_kernel<<<dim3(SS / 128, HH, BB), 256, FLASH_SMEM>>>(Qp, Kp, Vp, Cp);

    gemm_mma_kernel<false><<<ggrid, 256, GEMM_SMEM>>>(Cp, Wo, bo, out);
}